// round 3
// baseline (speedup 1.0000x reference)
#include <cuda_runtime.h>
#include <cuda_fp16.h>

#define WARPS_PER_BLOCK 8
#define THREADS (WARPS_PER_BLOCK * 32)
#define NUM_BLOCKS 2048
#define R 8                      // rows per warp (one group per warp at N=131072)

#define EMB_ELEMS (7424 * 128)
__device__ __half g_emb_h[EMB_ELEMS];   // fp16 repacked embedding table (1.9 MB)

__global__ void cvt_emb_kernel(const float* __restrict__ emb, int n)
{
    int i = blockIdx.x * blockDim.x + threadIdx.x;
    if (i < n) g_emb_h[i] = __float2half(emb[i]);
}

__global__ __launch_bounds__(THREADS)
void silk_nnue_kernel(const int*   __restrict__ x,
                      const float* __restrict__ W2,
                      const float* __restrict__ b2,
                      const float* __restrict__ W3,
                      const float* __restrict__ b3,
                      const float* __restrict__ W4,
                      float*       __restrict__ out,
                      int nrows)
{
    // Weights fp32, padded stride 132/68 floats => lane bank-advance 4,
    // conflict-free 32-lane LDS.128 sweeps.
    __shared__ float  sW2[32 * 132];
    __shared__ float  sW3[32 * 68];
    __shared__ float  sb2[32], sb3[32], sW4[64];
    // Per-warp activations in fp16: h (128 halves/row), later reused for CReLU a (64 halves/row).
    __shared__ __half sh[WARPS_PER_BLOCK][R * 128];

    const int tid = threadIdx.x;

    for (int i = tid; i < 32 * 128; i += THREADS)
        sW2[(i >> 7) * 132 + (i & 127)] = W2[i];
    for (int i = tid; i < 32 * 64; i += THREADS)
        sW3[(i >> 6) * 68 + (i & 63)] = W3[i];
    if (tid < 32)        sb2[tid]      = b2[tid];
    else if (tid < 64)   sb3[tid - 32] = b3[tid - 32];
    else if (tid < 128)  sW4[tid - 64] = W4[tid - 64];
    __syncthreads();

    const int lane = tid & 31;
    const int w    = tid >> 5;

    const float bias2 = sb2[lane];
    const float bias3 = sb3[lane];
    const float w4lo  = sW4[lane];
    const float w4hi  = sW4[lane + 32];

    __half* shw = sh[w];
    const uint2*  embh2 = (const uint2*)g_emb_h;
    const float4* wrow2 = (const float4*)(sW2 + lane * 132);
    const float4* wrow3 = (const float4*)(sW3 + lane * 68);

    const int gwarp = blockIdx.x * WARPS_PER_BLOCK + w;
    const int row0  = gwarp * R;
    if (row0 >= nrows) return;
    const bool full = (row0 + R <= nrows);

    // Lane l holds index slot l of each of the R rows.
    int xi[R];
    #pragma unroll
    for (int r = 0; r < R; ++r) {
        int row = row0 + r;
        xi[r] = (full || row < nrows) ? x[row * 32 + lane] : 0;
    }

    // ---- Gather-sum: 29*R coalesced 256B fp16 loads, fp32 accumulate ----
    float4 acc[R];
    #pragma unroll
    for (int r = 0; r < R; ++r) acc[r] = make_float4(0.f, 0.f, 0.f, 0.f);

    for (int j = 0; j < 29; ++j) {          // dynamic loop: keeps I-footprint small
        #pragma unroll
        for (int r = 0; r < R; ++r) {
            int idx = __shfl_sync(0xffffffffu, xi[r], j);
            uint2 v = __ldg(embh2 + (size_t)idx * 32 + lane);
            float2 lo = __half22float2(*(const __half2*)&v.x);
            float2 hi = __half22float2(*(const __half2*)&v.y);
            acc[r].x += lo.x; acc[r].y += lo.y;
            acc[r].z += hi.x; acc[r].w += hi.y;
        }
    }

    // ReLU + store h as fp16 (4 halves = 8B per lane per row -> STS.64)
    #pragma unroll
    for (int r = 0; r < R; ++r) {
        float4 a = acc[r];
        __half2 p0 = __floats2half2_rn(fmaxf(a.x, 0.f), fmaxf(a.y, 0.f));
        __half2 p1 = __floats2half2_rn(fmaxf(a.z, 0.f), fmaxf(a.w, 0.f));
        uint2 pk;
        pk.x = *(const unsigned*)&p0;
        pk.y = *(const unsigned*)&p1;
        *(uint2*)(shw + r * 128 + lane * 4) = pk;
    }
    __syncwarp();

    // ---- Layer 2: h2[lane] = b2 + W2[lane] . h   (weights amortized over R) ----
    float h2[R];
    #pragma unroll
    for (int r = 0; r < R; ++r) h2[r] = bias2;

    #pragma unroll 4
    for (int c = 0; c < 16; ++c) {          // 8 k's per chunk
        float4 w0 = wrow2[2 * c];
        float4 w1 = wrow2[2 * c + 1];
        #pragma unroll
        for (int r = 0; r < R; ++r) {
            uint4 hv = *(const uint4*)(shw + r * 128 + c * 8);   // 16B broadcast
            float2 f0 = __half22float2(*(const __half2*)&hv.x);
            float2 f1 = __half22float2(*(const __half2*)&hv.y);
            float2 f2 = __half22float2(*(const __half2*)&hv.z);
            float2 f3 = __half22float2(*(const __half2*)&hv.w);
            h2[r] = fmaf(w0.x, f0.x, h2[r]);
            h2[r] = fmaf(w0.y, f0.y, h2[r]);
            h2[r] = fmaf(w0.z, f1.x, h2[r]);
            h2[r] = fmaf(w0.w, f1.y, h2[r]);
            h2[r] = fmaf(w1.x, f2.x, h2[r]);
            h2[r] = fmaf(w1.y, f2.y, h2[r]);
            h2[r] = fmaf(w1.z, f3.x, h2[r]);
            h2[r] = fmaf(w1.w, f3.y, h2[r]);
        }
    }

    // ---- CReLU -> a (64 halves/row), reuse sh region ----
    __syncwarp();
    #pragma unroll
    for (int r = 0; r < R; ++r) {
        shw[r * 128 + lane]      = __float2half(fmaxf(h2[r], 0.f));
        shw[r * 128 + lane + 32] = __float2half(fmaxf(-h2[r], 0.f));
    }
    __syncwarp();

    // ---- Layer 3: h3[lane] = b3 + W3[lane] . a ----
    float h3[R];
    #pragma unroll
    for (int r = 0; r < R; ++r) h3[r] = bias3;

    #pragma unroll 2
    for (int c = 0; c < 8; ++c) {
        float4 w0 = wrow3[2 * c];
        float4 w1 = wrow3[2 * c + 1];
        #pragma unroll
        for (int r = 0; r < R; ++r) {
            uint4 av = *(const uint4*)(shw + r * 128 + c * 8);
            float2 f0 = __half22float2(*(const __half2*)&av.x);
            float2 f1 = __half22float2(*(const __half2*)&av.y);
            float2 f2 = __half22float2(*(const __half2*)&av.z);
            float2 f3 = __half22float2(*(const __half2*)&av.w);
            h3[r] = fmaf(w0.x, f0.x, h3[r]);
            h3[r] = fmaf(w0.y, f0.y, h3[r]);
            h3[r] = fmaf(w0.z, f1.x, h3[r]);
            h3[r] = fmaf(w0.w, f1.y, h3[r]);
            h3[r] = fmaf(w1.x, f2.x, h3[r]);
            h3[r] = fmaf(w1.y, f2.y, h3[r]);
            h3[r] = fmaf(w1.z, f3.x, h3[r]);
            h3[r] = fmaf(w1.w, f3.y, h3[r]);
        }
    }

    // ---- Layer 4 + warp reduction per row ----
    float part[R];
    #pragma unroll
    for (int r = 0; r < R; ++r) {
        float blo = fmaxf(h3[r], 0.f);
        float bhi = fmaxf(-h3[r], 0.f);
        part[r] = fmaf(w4lo, blo, w4hi * bhi);
        #pragma unroll
        for (int off = 16; off; off >>= 1)
            part[r] += __shfl_xor_sync(0xffffffffu, part[r], off);
    }

    if (lane == 0) {
        if (full) {
            *(float4*)(out + row0)     = make_float4(part[0], part[1], part[2], part[3]);
            *(float4*)(out + row0 + 4) = make_float4(part[4], part[5], part[6], part[7]);
        } else {
            for (int r = 0; r < R && row0 + r < nrows; ++r) out[row0 + r] = part[r];
        }
    }
}

extern "C" void kernel_launch(void* const* d_in, const int* in_sizes, int n_in,
                              void* d_out, int out_size)
{
    const int*   x   = (const int*)  d_in[0];
    const float* emb = (const float*)d_in[1];
    const float* W2  = (const float*)d_in[2];
    const float* b2  = (const float*)d_in[3];
    const float* W3  = (const float*)d_in[4];
    const float* b3  = (const float*)d_in[5];
    const float* W4  = (const float*)d_in[6];
    float* out = (float*)d_out;

    int nemb  = in_sizes[1];
    int nrows = in_sizes[0] / 32;

    cvt_emb_kernel<<<(nemb + 511) / 512, 512>>>(emb, nemb);

    int ngroups = (nrows + R - 1) / R;
    int nblocks = (ngroups + WARPS_PER_BLOCK - 1) / WARPS_PER_BLOCK;
    silk_nnue_kernel<<<nblocks, THREADS>>>(x, W2, b2, W3, b3, W4, out, nrows);
}

// round 4
// speedup vs baseline: 1.1678x; 1.1678x over previous
#include <cuda_runtime.h>
#include <cuda_fp16.h>

#define WPB 4
#define THREADS (WPB * 32)
#define R 8
#define NPAIR (R / 2)

#define EMB_ELEMS (7424 * 128)
__device__ __half g_emb_h[EMB_ELEMS];   // fp16 repacked embedding table (1.9 MB)

__global__ void cvt_emb_kernel(const float* __restrict__ emb, int n)
{
    int i = blockIdx.x * blockDim.x + threadIdx.x;
    if (i < n) g_emb_h[i] = __float2half(emb[i]);
}

// Packed 2-wide fp32 ops (Blackwell f32x2 pipe; PTX-only, no C++ autofuse).
__device__ __forceinline__ float2 ffma2(float2 a, float2 b, float2 c)
{
    float2 d;
    asm("{\n\t.reg .b64 ra,rb,rc,rd;\n\t"
        "mov.b64 ra,{%2,%3};\n\tmov.b64 rb,{%4,%5};\n\tmov.b64 rc,{%6,%7};\n\t"
        "fma.rn.f32x2 rd, ra, rb, rc;\n\t"
        "mov.b64 {%0,%1}, rd;\n\t}"
        : "=f"(d.x), "=f"(d.y)
        : "f"(a.x), "f"(a.y), "f"(b.x), "f"(b.y), "f"(c.x), "f"(c.y));
    return d;
}
__device__ __forceinline__ float2 fadd2(float2 a, float2 b)
{
    float2 d;
    asm("{\n\t.reg .b64 ra,rb,rd;\n\t"
        "mov.b64 ra,{%2,%3};\n\tmov.b64 rb,{%4,%5};\n\t"
        "add.rn.f32x2 rd, ra, rb;\n\t"
        "mov.b64 {%0,%1}, rd;\n\t}"
        : "=f"(d.x), "=f"(d.y)
        : "f"(a.x), "f"(a.y), "f"(b.x), "f"(b.y));
    return d;
}

__global__ __launch_bounds__(THREADS)
void silk_nnue_kernel(const int*   __restrict__ x,
                      const float* __restrict__ W2,
                      const float* __restrict__ b2,
                      const float* __restrict__ W3,
                      const float* __restrict__ b3,
                      const float* __restrict__ W4,
                      float*       __restrict__ out,
                      int nrows)
{
    // fp32 weights, padded stride 132/68 floats => conflict-free LDS.128 sweeps.
    __shared__ float  sW2[32 * 132];
    __shared__ float  sW3[32 * 68];
    __shared__ float  sb2[32], sb3[32], sW4[64];
    // Per-warp pair-interleaved activations: pair q, element k -> {row2q[k], row2q+1[k]}
    __shared__ float2 sh[WPB][NPAIR * 128];

    const int tid = threadIdx.x;

    for (int i = tid; i < 32 * 128; i += THREADS)
        sW2[(i >> 7) * 132 + (i & 127)] = W2[i];
    for (int i = tid; i < 32 * 64; i += THREADS)
        sW3[(i >> 6) * 68 + (i & 63)] = W3[i];
    if (tid < 32)       sb2[tid]      = b2[tid];
    else if (tid < 64)  sb3[tid - 32] = b3[tid - 32];
    if (tid < 64)       sW4[tid]      = W4[tid];
    __syncthreads();

    const int lane = tid & 31;
    const int w    = tid >> 5;

    const float bias2 = sb2[lane];
    const float bias3 = sb3[lane];
    const float2 w4lo2 = make_float2(sW4[lane],      sW4[lane]);
    const float2 w4hi2 = make_float2(sW4[lane + 32], sW4[lane + 32]);

    float2* shw = sh[w];
    const uint2*  embh2 = (const uint2*)g_emb_h;
    const float4* wrow2 = (const float4*)(sW2 + lane * 132);
    const float4* wrow3 = (const float4*)(sW3 + lane * 68);

    const int gwarp = blockIdx.x * WPB + w;
    const int row0  = gwarp * R;
    if (row0 >= nrows) return;
    const bool full = (row0 + R <= nrows);

    // Lane l holds index slot l of each of the R rows.
    int xi[R];
    #pragma unroll
    for (int r = 0; r < R; ++r) {
        int row = row0 + r;
        xi[r] = (full || row < nrows) ? x[row * 32 + lane] : 0;
    }

    // ---- Gather-sum: 29*R coalesced 256B fp16 loads, packed f32x2 accumulate ----
    float2 acc01[R], acc23[R];   // lane covers k = 4*lane .. 4*lane+3
    #pragma unroll
    for (int r = 0; r < R; ++r) {
        acc01[r] = make_float2(0.f, 0.f);
        acc23[r] = make_float2(0.f, 0.f);
    }

    for (int j = 0; j < 29; ++j) {
        #pragma unroll
        for (int r = 0; r < R; ++r) {
            int idx = __shfl_sync(0xffffffffu, xi[r], j);
            uint2 v = __ldg(embh2 + (size_t)idx * 32 + lane);
            float2 lo = __half22float2(*(const __half2*)&v.x);
            float2 hi = __half22float2(*(const __half2*)&v.y);
            acc01[r] = fadd2(acc01[r], lo);
            acc23[r] = fadd2(acc23[r], hi);
        }
    }

    // ReLU + pair-interleaved store: float4 {h0[k],h1[k],h0[k+1],h1[k+1]}
    #pragma unroll
    for (int q = 0; q < NPAIR; ++q) {
        const int r0 = 2 * q, r1 = 2 * q + 1;
        float4 s0 = make_float4(fmaxf(acc01[r0].x, 0.f), fmaxf(acc01[r1].x, 0.f),
                                fmaxf(acc01[r0].y, 0.f), fmaxf(acc01[r1].y, 0.f));
        float4 s1 = make_float4(fmaxf(acc23[r0].x, 0.f), fmaxf(acc23[r1].x, 0.f),
                                fmaxf(acc23[r0].y, 0.f), fmaxf(acc23[r1].y, 0.f));
        float4* hq = (float4*)(shw + q * 128);
        hq[2 * lane]     = s0;
        hq[2 * lane + 1] = s1;
    }
    __syncwarp();

    // ---- Layer 2: packed over row-pairs; weights amortized over 8 rows ----
    float2 h2p[NPAIR];
    #pragma unroll
    for (int q = 0; q < NPAIR; ++q) h2p[q] = make_float2(bias2, bias2);

    #pragma unroll 8
    for (int c = 0; c < 32; ++c) {              // 4 k per iteration
        float4 wv = wrow2[c];
        float2 wxx = make_float2(wv.x, wv.x);
        float2 wyy = make_float2(wv.y, wv.y);
        float2 wzz = make_float2(wv.z, wv.z);
        float2 www = make_float2(wv.w, wv.w);
        #pragma unroll
        for (int q = 0; q < NPAIR; ++q) {
            const float4* hq = (const float4*)(shw + q * 128);
            float4 p0 = hq[2 * c];              // k=4c, 4c+1 (broadcast)
            float4 p1 = hq[2 * c + 1];          // k=4c+2, 4c+3
            h2p[q] = ffma2(wxx, make_float2(p0.x, p0.y), h2p[q]);
            h2p[q] = ffma2(wyy, make_float2(p0.z, p0.w), h2p[q]);
            h2p[q] = ffma2(wzz, make_float2(p1.x, p1.y), h2p[q]);
            h2p[q] = ffma2(www, make_float2(p1.z, p1.w), h2p[q]);
        }
    }

    // ---- CReLU -> pair-interleaved a (64 entries/pair), reuse sh region ----
    __syncwarp();
    #pragma unroll
    for (int q = 0; q < NPAIR; ++q) {
        float2 alo = make_float2(fmaxf(h2p[q].x, 0.f), fmaxf(h2p[q].y, 0.f));
        float2 ahi = make_float2(fmaxf(-h2p[q].x, 0.f), fmaxf(-h2p[q].y, 0.f));
        shw[q * 64 + lane]      = alo;
        shw[q * 64 + lane + 32] = ahi;
    }
    __syncwarp();

    // ---- Layer 3 ----
    float2 h3p[NPAIR];
    #pragma unroll
    for (int q = 0; q < NPAIR; ++q) h3p[q] = make_float2(bias3, bias3);

    #pragma unroll 4
    for (int c = 0; c < 16; ++c) {
        float4 wv = wrow3[c];
        float2 wxx = make_float2(wv.x, wv.x);
        float2 wyy = make_float2(wv.y, wv.y);
        float2 wzz = make_float2(wv.z, wv.z);
        float2 www = make_float2(wv.w, wv.w);
        #pragma unroll
        for (int q = 0; q < NPAIR; ++q) {
            const float4* aq = (const float4*)(shw + q * 64);
            float4 p0 = aq[2 * c];
            float4 p1 = aq[2 * c + 1];
            h3p[q] = ffma2(wxx, make_float2(p0.x, p0.y), h3p[q]);
            h3p[q] = ffma2(wyy, make_float2(p0.z, p0.w), h3p[q]);
            h3p[q] = ffma2(wzz, make_float2(p1.x, p1.y), h3p[q]);
            h3p[q] = ffma2(www, make_float2(p1.z, p1.w), h3p[q]);
        }
    }

    // ---- Layer 4 + packed warp reduction (both rows of a pair at once) ----
    float2 part[NPAIR];
    #pragma unroll
    for (int q = 0; q < NPAIR; ++q) {
        float2 blo = make_float2(fmaxf(h3p[q].x, 0.f), fmaxf(h3p[q].y, 0.f));
        float2 bhi = make_float2(fmaxf(-h3p[q].x, 0.f), fmaxf(-h3p[q].y, 0.f));
        float2 p = ffma2(w4hi2, bhi, make_float2(0.f, 0.f));
        p = ffma2(w4lo2, blo, p);
        #pragma unroll
        for (int off = 16; off; off >>= 1) {
            float2 o;
            o.x = __shfl_xor_sync(0xffffffffu, p.x, off);
            o.y = __shfl_xor_sync(0xffffffffu, p.y, off);
            p = fadd2(p, o);
        }
        part[q] = p;
    }

    if (lane == 0) {
        if (full) {
            *(float4*)(out + row0) =
                make_float4(part[0].x, part[0].y, part[1].x, part[1].y);
            *(float4*)(out + row0 + 4) =
                make_float4(part[2].x, part[2].y, part[3].x, part[3].y);
        } else {
            float pr[R] = {part[0].x, part[0].y, part[1].x, part[1].y,
                           part[2].x, part[2].y, part[3].x, part[3].y};
            for (int r = 0; r < R && row0 + r < nrows; ++r) out[row0 + r] = pr[r];
        }
    }
}

extern "C" void kernel_launch(void* const* d_in, const int* in_sizes, int n_in,
                              void* d_out, int out_size)
{
    const int*   x   = (const int*)  d_in[0];
    const float* emb = (const float*)d_in[1];
    const float* W2  = (const float*)d_in[2];
    const float* b2  = (const float*)d_in[3];
    const float* W3  = (const float*)d_in[4];
    const float* b3  = (const float*)d_in[5];
    const float* W4  = (const float*)d_in[6];
    float* out = (float*)d_out;

    int nemb  = in_sizes[1];
    int nrows = in_sizes[0] / 32;

    cvt_emb_kernel<<<(nemb + 511) / 512, 512>>>(emb, nemb);

    int ngroups = (nrows + R - 1) / R;
    int nblocks = (ngroups + WPB - 1) / WPB;
    silk_nnue_kernel<<<nblocks, THREADS>>>(x, W2, b2, W3, b3, W4, out, nrows);
}